// round 17
// baseline (speedup 1.0000x reference)
#include <cuda_runtime.h>
#include <cstdint>

// PointConv: B=32, C=64, H=W=64, KH=KW=2 -> L=1024, n=256.
// Per l: D[p, b] = sum_k W[l][k][p] * patch[b][k] + bias[p, l]
// fp32 via 3-term bf16 split on mma.sync.m16n8k16.
// R17: R14 (register-direct A fragments, barrier-free mainloop) + 3-bank
//      2-stage LDG lookahead so W loads get ~2 stages to complete.

#define HH 64
#define CC 64
#define NN 256
#define LL 1024

#define KSTAGE 16
#define NSTG   16

#define OFF_P 0                    // frag stream: 16 s x 4 nt x 512B = 32768
#define SMEM_TOTAL 32768

__device__ __forceinline__ uint32_t cvt2(float lo, float hi) {  // pack {lo=low16, hi=high16}
    uint32_t r;
    asm("cvt.rn.bf16x2.f32 %0, %1, %2;" : "=r"(r) : "f"(hi), "f"(lo));
    return r;
}
__device__ __forceinline__ float lo_f(uint32_t p) { return __uint_as_float(p << 16); }
__device__ __forceinline__ float hi_f(uint32_t p) { return __uint_as_float(p & 0xffff0000u); }

__device__ __forceinline__ void mma_bf16(float* d, const uint32_t* a, uint32_t b0, uint32_t b1) {
    asm volatile(
        "mma.sync.aligned.m16n8k16.row.col.f32.bf16.bf16.f32 "
        "{%0,%1,%2,%3}, {%4,%5,%6,%7}, {%8,%9}, {%0,%1,%2,%3};"
        : "+f"(d[0]), "+f"(d[1]), "+f"(d[2]), "+f"(d[3])
        : "r"(a[0]), "r"(a[1]), "r"(a[2]), "r"(a[3]), "r"(b0), "r"(b1));
}

__device__ __forceinline__ void load_raw(float* r, const float* bp) {
    r[0] = bp[0];          r[1] = bp[NN];
    r[2] = bp[8];          r[3] = bp[NN + 8];
    r[4] = bp[8 * NN];     r[5] = bp[9 * NN];
    r[6] = bp[8 * NN + 8]; r[7] = bp[9 * NN + 8];
}

__global__ void __launch_bounds__(256, 2)
pointconv_mma(const float* __restrict__ x,
              const float* __restrict__ w,
              const float* __restrict__ bias,
              float* __restrict__ out)
{
    extern __shared__ char smem[];
    const int tid  = threadIdx.x;
    const int wid  = tid >> 5;                  // 0..7
    const int lane = tid & 31;
    const int l    = blockIdx.x;
    const int ph = l >> 5, pw = l & 31;
    const float* __restrict__ wl = w + (size_t)l * (NN * NN);

    // ---- patch gather -> bf16 hi/mid split -> fragment stream ----
    {
        const int b  = tid & 31;
        const int cg = tid >> 5;
        #pragma unroll
        for (int ci = 0; ci < 8; ci++) {
            const int c = cg * 8 + ci;
            #pragma unroll
            for (int kh = 0; kh < 2; kh++) {
                const float2 v = *reinterpret_cast<const float2*>(
                    x + (size_t)(((b * CC + c) * HH + 2 * ph + kh) * HH + 2 * pw));
                const int k  = c * 4 + kh * 2;            // even
                const int s  = k >> 4;
                const int kk = k & 15;
                const int t  = (kk >> 1) & 3;
                const int hi8 = (kk >= 8) ? 1 : 0;
                const uint32_t hp = cvt2(v.x, v.y);
                const uint32_t mp = cvt2(v.x - lo_f(hp), v.y - hi_f(hp));
                char* dst = smem + OFF_P + ((s * 4 + (b >> 3)) * 512) + (((b & 7) * 4 + t) * 16);
                *reinterpret_cast<uint32_t*>(dst + hi8 * 4)     = hp;
                *reinterpret_cast<uint32_t*>(dst + 8 + hi8 * 4) = mp;
            }
        }
    }

    float d[2][4][4];
    #pragma unroll
    for (int i = 0; i < 2; i++)
        #pragma unroll
        for (int j = 0; j < 4; j++)
            #pragma unroll
            for (int r = 0; r < 4; r++) d[i][j][r] = 0.0f;

    const int wbase = wid * 32;                 // warp's p slice
    const int g = lane >> 2;
    const int c = (lane & 3) * 2;

    // per-lane A base: wl[(k=c)*NN + (p = wbase + g)]; ptile 1 adds +16.
    const float* __restrict__ lbase = wl + (size_t)c * NN + wbase + g;

    // ---- 3-bank raw storage, 2-stage lookahead ----
    float raw[3][2][8];
    #pragma unroll
    for (int pt = 0; pt < 2; pt++) load_raw(raw[0][pt], lbase + pt * 16);
    #pragma unroll
    for (int pt = 0; pt < 2; pt++)
        load_raw(raw[1][pt], lbase + (size_t)KSTAGE * NN + pt * 16);

    __syncthreads();                            // frag stream visible

    // ---- mainloop: barrier-free, register-direct A fragments ----
    int bank = 0;
    #pragma unroll 1
    for (int s = 0; s < NSTG; s++) {
        const int nb = (bank + 2 >= 3) ? bank - 1 : bank + 2;   // (s+2)%3

        // issue stage s+2 loads FIRST (2-stage latency budget)
        if (s + 2 < NSTG) {
            const float* sb = lbase + (size_t)(s + 2) * KSTAGE * NN;
            #pragma unroll
            for (int pt = 0; pt < 2; pt++) load_raw(raw[nb][pt], sb + pt * 16);
        }

        // convert current bank -> A fragments (hi + mid)
        uint32_t ah[2][4], am[2][4];
        #pragma unroll
        for (int pt = 0; pt < 2; pt++)
            #pragma unroll
            for (int j = 0; j < 4; j++) {
                const float v0 = raw[bank][pt][j * 2];
                const float v1 = raw[bank][pt][j * 2 + 1];
                const uint32_t h = cvt2(v0, v1);
                ah[pt][j] = h;
                am[pt][j] = cvt2(v0 - lo_f(h), v1 - hi_f(h));
            }

        // B fragments: 4 x LDS.128 from the pre-formatted stream
        uint4 bf[4];
        #pragma unroll
        for (int nt = 0; nt < 4; nt++)
            bf[nt] = *reinterpret_cast<const uint4*>(
                smem + OFF_P + (s * 4 + nt) * 512 + lane * 16);

        #pragma unroll
        for (int pt = 0; pt < 2; pt++)
            #pragma unroll
            for (int nt = 0; nt < 4; nt++) {
                mma_bf16(d[pt][nt], ah[pt], bf[nt].x, bf[nt].y);   // hi * hi
                mma_bf16(d[pt][nt], ah[pt], bf[nt].z, bf[nt].w);   // hi * mid
                mma_bf16(d[pt][nt], am[pt], bf[nt].x, bf[nt].y);   // mid * hi
            }

        bank = (bank + 1 >= 3) ? 0 : bank + 1;
    }

    // ---- epilogue: bias + scatter ----
    #pragma unroll
    for (int pt = 0; pt < 2; pt++) {
        const int p0 = wbase + pt * 16 + (lane >> 2);
        const int p1 = p0 + 8;
        const float bv0 = bias[p0 * LL + l];
        const float bv1 = bias[p1 * LL + l];
        const int c0 = p0 >> 2, kh0 = (p0 >> 1) & 1, kw0 = p0 & 1;
        const int c1 = p1 >> 2, kh1 = (p1 >> 1) & 1, kw1 = p1 & 1;
        #pragma unroll
        for (int nt = 0; nt < 4; nt++) {
            const int b = nt * 8 + 2 * (lane & 3);
            const size_t o0 = (size_t)(((b * CC + c0) * HH + 2 * ph + kh0) * HH + 2 * pw + kw0);
            const size_t o1 = (size_t)(((b * CC + c1) * HH + 2 * ph + kh1) * HH + 2 * pw + kw1);
            const size_t bs = (size_t)CC * HH * HH;
            out[o0]      = d[pt][nt][0] + bv0;
            out[o0 + bs] = d[pt][nt][1] + bv0;
            out[o1]      = d[pt][nt][2] + bv1;
            out[o1 + bs] = d[pt][nt][3] + bv1;
        }
    }
}

extern "C" void kernel_launch(void* const* d_in, const int* in_sizes, int n_in,
                              void* d_out, int out_size)
{
    const float* x    = (const float*)d_in[0];
    const float* w    = (const float*)d_in[1];
    const float* bias = (const float*)d_in[2];
    float* out        = (float*)d_out;

    cudaFuncSetAttribute(pointconv_mma,
                         cudaFuncAttributeMaxDynamicSharedMemorySize, SMEM_TOTAL);
    pointconv_mma<<<LL, 256, SMEM_TOTAL>>>(x, w, bias, out);
}